// round 17
// baseline (speedup 1.0000x reference)
#include <cuda_runtime.h>
#include <math.h>
#include <stdint.h>

// Problem constants
#define BB    8
#define CC    512
#define NN    1024        // H*W = 32*32
#define HEADS 8
#define DK    64
#define QKVC  1536        // HEADS * DK * 3
#define SCL2E 0.18033688f // DK^-0.5 * log2(e)

// ---------------------------------------------------------------------------
// Scratch (device globals; no allocation allowed) — fp16 planes
// ---------------------------------------------------------------------------
__device__ uint16_t g_xh[BB * CC * NN];                          // x fp16
__device__ uint16_t g_wqh[CC * QKVC];                            // W_qkv fp16
__device__ uint16_t g_woh[CC * CC];                              // W_out fp16
__device__ uint16_t g_qh[BB * NN * QKVC];                        // qkv (Q pre-scaled)
__device__ uint16_t g_ah[BB * NN * CC];                          // attention out

// ---------------------------------------------------------------------------
// Helpers
// ---------------------------------------------------------------------------
__device__ __forceinline__ float ex2(float x) {
    float y;
    asm("ex2.approx.f32 %0, %1;" : "=f"(y) : "f"(x));
    return y;
}
__device__ __forceinline__ uint32_t hi2(float f0, float f1) {   // {f16(f0)|f16(f1)<<16}
    uint32_t r;
    asm("cvt.rn.f16x2.f32 %0, %1, %2;" : "=r"(r) : "f"(f1), "f"(f0));
    return r;
}

__device__ __forceinline__ void cpa16(uint32_t dst, const void* src) {
    asm volatile("cp.async.cg.shared.global [%0], [%1], 16;" :: "r"(dst), "l"(src));
}
#define CP_COMMIT() asm volatile("cp.async.commit_group;" ::: "memory")
#define CP_WAIT2()  asm volatile("cp.async.wait_group 2;" ::: "memory")
#define CP_WAIT1()  asm volatile("cp.async.wait_group 1;" ::: "memory")
#define CP_WAIT0()  asm volatile("cp.async.wait_group 0;" ::: "memory")
#define CP_WAIT_TAIL(s, last) do {                                            \
        if ((s) < (last) - 1)      CP_WAIT2();                                \
        else if ((s) == (last) - 1) CP_WAIT1();                               \
        else                        CP_WAIT0();                               \
    } while (0)

__device__ __forceinline__ void ldmx4t(uint32_t addr, uint32_t& r0, uint32_t& r1,
                                       uint32_t& r2, uint32_t& r3) {
    asm volatile("ldmatrix.sync.aligned.m8n8.x4.trans.shared.b16 {%0,%1,%2,%3}, [%4];"
                 : "=r"(r0), "=r"(r1), "=r"(r2), "=r"(r3) : "r"(addr));
}
__device__ __forceinline__ void ldmx4(uint32_t addr, uint32_t* r) {
    asm volatile("ldmatrix.sync.aligned.m8n8.x4.shared.b16 {%0,%1,%2,%3}, [%4];"
                 : "=r"(r[0]), "=r"(r[1]), "=r"(r[2]), "=r"(r[3]) : "r"(addr));
}
__device__ __forceinline__ void mma16816(float* d, const uint32_t* a, const uint32_t* b) {
    asm volatile("mma.sync.aligned.m16n8k16.row.col.f32.f16.f16.f32 "
                 "{%0,%1,%2,%3}, {%4,%5,%6,%7}, {%8,%9}, {%0,%1,%2,%3};"
                 : "+f"(d[0]), "+f"(d[1]), "+f"(d[2]), "+f"(d[3])
                 : "r"(a[0]), "r"(a[1]), "r"(a[2]), "r"(a[3]), "r"(b[0]), "r"(b[1]));
}
__device__ __forceinline__ void mma_b(float* d, const uint32_t* a, uint32_t b0, uint32_t b1) {
    asm volatile("mma.sync.aligned.m16n8k16.row.col.f32.f16.f16.f32 "
                 "{%0,%1,%2,%3}, {%4,%5,%6,%7}, {%8,%9}, {%0,%1,%2,%3};"
                 : "+f"(d[0]), "+f"(d[1]), "+f"(d[2]), "+f"(d[3])
                 : "r"(a[0]), "r"(a[1]), "r"(a[2]), "r"(a[3]), "r"(b0), "r"(b1));
}

// ---------------------------------------------------------------------------
// Kernel 0: fp32 -> fp16 (all three tensors, one launch)
// ---------------------------------------------------------------------------
#define NX4  (BB * CC * NN / 4)
#define NWQ4 (CC * QKVC / 4)
#define NWO4 (CC * CC / 4)

__global__ __launch_bounds__(256) void k_cvt(const float* __restrict__ x,
                                             const float* __restrict__ Wq,
                                             const float* __restrict__ Wo)
{
    int i = blockIdx.x * blockDim.x + threadIdx.x;
    const float* src;
    uint16_t* dst;
    int j;
    if (i < NX4)                { src = x;  dst = g_xh;  j = i; }
    else if (i < NX4 + NWQ4)    { src = Wq; dst = g_wqh; j = i - NX4; }
    else if (i < NX4 + NWQ4 + NWO4) { src = Wo; dst = g_woh; j = i - NX4 - NWQ4; }
    else return;
    float4 v = ((const float4*)src)[j];
    ((uint2*)dst)[j] = make_uint2(hi2(v.x, v.y), hi2(v.z, v.w));
}

// ---------------------------------------------------------------------------
// Kernel 1: QKV GEMM, tensor cores (fp16), cp.async 4-stage, 8 warps,
// warp tile 64x32.  Output fp16 plane, Q pre-scaled.
// ---------------------------------------------------------------------------
#define KBYTES  8704            // one plane: 32 * 272 B
#define QK_STG  (2 * KBYTES)    // 17408 B per stage
#define QK_SMEM (4 * QK_STG)    // 69632 B

__global__ __launch_bounds__(256) void k_qkv(const float* __restrict__ bq)
{
    extern __shared__ __align__(16) uint16_t smq[];
    const int tid  = threadIdx.x;
    const int lane = tid & 31;
    const int wid  = tid >> 5;
    const int bx   = blockIdx.x;          // c tile 0..11
    const int by   = blockIdx.y;          // m tile 0..63
    const int b    = by >> 3;
    const int n0   = (by & 7) << 7;
    const int c0   = bx * 128;
    const uint32_t sbase = (uint32_t)__cvta_generic_to_shared(smq);

    // loader mapping: row lk (0..31), 16 u16 (32B) per plane per matrix
    const int lk  = tid >> 3;
    const int lmf = (tid & 7) * 16;
    const size_t aG = (size_t)b * CC * NN + n0 + lmf + (size_t)lk * NN;
    const size_t wG = (size_t)c0 + lmf + (size_t)lk * QKVC;
    const uint32_t dA = (uint32_t)(lk * 136 + lmf) * 2;

    const int wm = wid >> 2;
    const int wn = wid & 3;
    const uint32_t aOff = ((lane & 7) + ((lane >> 4) << 3)) * 272
                        + (uint32_t)(wm * 128) + ((lane >> 3) & 1) * 16;
    const uint32_t bOff = ((lane & 7) + (((lane >> 3) & 1) << 3)) * 272
                        + (uint32_t)(wn * 64) + (lane >> 4) * 16;

    float acc[4][4][4];
#pragma unroll
    for (int i = 0; i < 4; i++)
#pragma unroll
        for (int j = 0; j < 4; j++)
#pragma unroll
            for (int e = 0; e < 4; e++) acc[i][j][e] = 0.f;

#define QK_ISSUE(s) do {                                                      \
        uint32_t st = sbase + ((s) & 3) * QK_STG;                             \
        size_t ko = (size_t)(s) * 32;                                         \
        const uint16_t* ah = &g_xh[aG + ko * NN];                             \
        const uint16_t* wh = &g_wqh[wG + ko * QKVC];                          \
        cpa16(st + dA, ah);              cpa16(st + dA + 16, ah + 8);         \
        cpa16(st + dA + KBYTES, wh);     cpa16(st + dA + KBYTES + 16, wh + 8);\
    } while (0)

    QK_ISSUE(0); CP_COMMIT();
    QK_ISSUE(1); CP_COMMIT();
    QK_ISSUE(2); CP_COMMIT();

    for (int s = 0; s < 16; s++) {
        CP_WAIT_TAIL(s, 15);
        __syncthreads();
        if (s + 3 < 16) { QK_ISSUE(s + 3); CP_COMMIT(); }

        const uint32_t base = sbase + (uint32_t)(s & 3) * QK_STG;
#pragma unroll
        for (int ks = 0; ks < 2; ks++) {
            uint32_t ahi[4][4], bhi[4][2];
#pragma unroll
            for (int i = 0; i < 4; i++) {
                uint32_t addr = base + aOff + ks * 4352 + i * 32;
                ldmx4t(addr, ahi[i][0], ahi[i][1], ahi[i][2], ahi[i][3]);
            }
#pragma unroll
            for (int j2 = 0; j2 < 2; j2++) {
                uint32_t addr = base + KBYTES + bOff + ks * 4352 + j2 * 32;
                ldmx4t(addr, bhi[2 * j2][0], bhi[2 * j2][1], bhi[2 * j2 + 1][0], bhi[2 * j2 + 1][1]);
            }
#pragma unroll
            for (int i = 0; i < 4; i++)
#pragma unroll
                for (int jn = 0; jn < 4; jn++)
                    mma16816(acc[i][jn], ahi[i], bhi[jn]);
        }
    }

    // ---- epilogue: bias, pre-scale Q columns, store fp16 ----
    const int g   = lane >> 2;
    const int tig = lane & 3;
#pragma unroll
    for (int i = 0; i < 4; i++) {
        int m = by * 128 + wm * 64 + i * 16 + g;
#pragma unroll
        for (int jn = 0; jn < 4; jn++) {
            int c = c0 + wn * 32 + jn * 8 + tig * 2;
            float2 bias = *(const float2*)&bq[c];
            float sc = ((c % 192) < 64) ? SCL2E : 1.f;
            float v0 = (acc[i][jn][0] + bias.x) * sc;
            float v1 = (acc[i][jn][1] + bias.y) * sc;
            float v2 = (acc[i][jn][2] + bias.x) * sc;
            float v3 = (acc[i][jn][3] + bias.y) * sc;
            *(uint32_t*)&g_qh[(size_t)m * QKVC + c]       = hi2(v0, v1);
            *(uint32_t*)&g_qh[(size_t)(m + 8) * QKVC + c] = hi2(v2, v3);
        }
    }
}

// ---------------------------------------------------------------------------
// Kernel 2: attention, tensor cores (fp16), 8 warps x 16 q-rows,
// K/V stages of 64 keys TRIPLE buffered.
// Smem: Qh (128x72 u16) + 3 stages of {Kh, Vh} (64x72 each) = 73728 B.
// ---------------------------------------------------------------------------
#define A_ST0   9216            // u16: stage region start (after Qh)
#define A_STG   9216            // u16 per stage (2 planes * 64*72)
#define A_VHIo  4608            // V within stage (u16)
#define A_SMEM_BYTES ((A_ST0 + 3 * A_STG) * 2)   // 73728 B

__global__ __launch_bounds__(256, 2) void k_attn()
{
    extern __shared__ __align__(16) uint16_t sma[];
    const int tid  = threadIdx.x;
    const int lane = tid & 31;
    const int wid  = tid >> 5;     // 0..7
    const int qt   = blockIdx.x;   // 0..7
    const int h    = blockIdx.y;
    const int b    = blockIdx.z;
    const size_t head = (size_t)b * NN * QKVC + (size_t)h * (3 * DK);
    const uint32_t sb = (uint32_t)__cvta_generic_to_shared(sma);

    // Q loader: row = tid>>1 (0..127), off = (tid&1)*32 u16 (4 chunks)
    const int qrow = tid >> 1;
    const int qoff = (tid & 1) * 32;
    const uint32_t dQ = (uint32_t)(qrow * 72 + qoff) * 2;
#define AT_ISSUE_Q() do {                                                     \
        size_t rr = head + (size_t)(qt * 128 + qrow) * QKVC + qoff;           \
        const uint16_t* qh_ = &g_qh[rr];                                      \
        _Pragma("unroll")                                                     \
        for (int cc = 0; cc < 4; cc++)                                        \
            cpa16(sb + dQ + cc * 16, qh_ + cc * 8);                           \
    } while (0)

    // KV loader: key row = tid>>2 (0..63), quarter-row 16 u16 (2 chunks/plane)
    const int lrow = tid >> 2;
    const int loff = (tid & 3) * 16;
    const uint32_t dKV = (uint32_t)(lrow * 72 + loff) * 2;
#define AT_ISSUE_KV(kt) do {                                                  \
        uint32_t st = sb + (A_ST0 + ((kt) % 3) * A_STG) * 2;                  \
        size_t rr = head + (size_t)((kt) * 64 + lrow) * QKVC + loff;          \
        const uint16_t* kh_ = &g_qh[rr + 64];                                 \
        const uint16_t* vh_ = &g_qh[rr + 128];                                \
        _Pragma("unroll")                                                     \
        for (int cc = 0; cc < 2; cc++) {                                      \
            cpa16(st + dKV + cc * 16,              kh_ + cc * 8);             \
            cpa16(st + dKV + A_VHIo * 2 + cc * 16, vh_ + cc * 8);             \
        }                                                                     \
    } while (0)

    AT_ISSUE_Q(); AT_ISSUE_KV(0); CP_COMMIT();
    AT_ISSUE_KV(1); CP_COMMIT();
    AT_ISSUE_KV(2); CP_COMMIT();

    const uint32_t kOff = ((lane & 7) + ((lane >> 4) << 3)) * 144
                        + ((lane >> 3) & 1) * 16;                 // non-trans (K)
    const uint32_t vOff = ((lane & 7) + (((lane >> 3) & 1) << 3)) * 144
                        + (lane >> 4) * 16;                        // trans (V)

    uint32_t qf[4][4];
    float oacc[8][4];
#pragma unroll
    for (int i = 0; i < 8; i++)
#pragma unroll
        for (int e = 0; e < 4; e++) oacc[i][e] = 0.f;
    float li0 = 0.f, li1 = 0.f;

    for (int kt = 0; kt < 16; kt++) {
        CP_WAIT_TAIL(kt, 15);
        __syncthreads();

        if (kt == 0) {
            const uint32_t qa = sb + (wid * 16 + (lane & 15)) * 144 + (lane >> 4) * 16;
#pragma unroll
            for (int j = 0; j < 4; j++) ldmx4(qa + j * 32, qf[j]);
        }

        const uint32_t stb = sb + (A_ST0 + (kt % 3) * A_STG) * 2;
        const uint32_t kB = stb + kOff;
        const uint32_t vB = stb + A_VHIo * 2 + vOff;

        // ---- fused per 16-key group: S (2 n8-tiles) -> exp -> P -> PV ----
#pragma unroll
        for (int nt2 = 0; nt2 < 4; nt2++) {
            float s0[4], s1[4];
#pragma unroll
            for (int e = 0; e < 4; e++) { s0[e] = 0.f; s1[e] = 0.f; }

#pragma unroll
            for (int j = 0; j < 4; j++) {
                uint32_t kh[4];
                uint32_t a = kB + nt2 * (16 * 144) + j * 32;
                ldmx4(a, kh);
                mma_b(s0, qf[j], kh[0], kh[1]);
                mma_b(s1, qf[j], kh[2], kh[3]);
            }

#pragma unroll
            for (int e = 0; e < 4; e++) { s0[e] = ex2(s0[e]); s1[e] = ex2(s1[e]); }
            li0 += (s0[0] + s0[1]) + (s1[0] + s1[1]);
            li1 += (s0[2] + s0[3]) + (s1[2] + s1[3]);

            uint32_t ph[4];
            ph[0] = hi2(s0[0], s0[1]); ph[1] = hi2(s0[2], s0[3]);
            ph[2] = hi2(s1[0], s1[1]); ph[3] = hi2(s1[2], s1[3]);

#pragma unroll
            for (int dt2 = 0; dt2 < 4; dt2++) {
                uint32_t vh0, vh1, vh2, vh3;
                uint32_t a = vB + nt2 * (16 * 144) + dt2 * 32;
                ldmx4t(a, vh0, vh1, vh2, vh3);
                mma_b(oacc[2 * dt2],     ph, vh0, vh1);
                mma_b(oacc[2 * dt2 + 1], ph, vh2, vh3);
            }
        }

        __syncthreads();   // stage (kt%3) fully consumed before refill
        if (kt + 3 < 16) { AT_ISSUE_KV(kt + 3); CP_COMMIT(); }
    }

    // ---- reduce row sums over the 4 quad lanes, normalize, write fp16 ----
    li0 += __shfl_xor_sync(0xffffffffu, li0, 1);
    li0 += __shfl_xor_sync(0xffffffffu, li0, 2);
    li1 += __shfl_xor_sync(0xffffffffu, li1, 1);
    li1 += __shfl_xor_sync(0xffffffffu, li1, 2);
    const float inv0 = 1.f / li0;
    const float inv1 = 1.f / li1;

    const int g   = lane >> 2;
    const int tig = lane & 3;
    const int row = qt * 128 + wid * 16 + g;
    const size_t r0 = (size_t)(b * NN + row) * CC + h * 64 + tig * 2;
    const size_t r1 = r0 + (size_t)8 * CC;
#pragma unroll
    for (int dt = 0; dt < 8; dt++) {
        *(uint32_t*)&g_ah[r0 + dt * 8] = hi2(oacc[dt][0] * inv0, oacc[dt][1] * inv0);
        *(uint32_t*)&g_ah[r1 + dt * 8] = hi2(oacc[dt][2] * inv1, oacc[dt][3] * inv1);
    }
}

// ---------------------------------------------------------------------------
// Kernel 3: out = att @ W_out + b_out + residual (fp16), cp.async 4-stage;
// smem-transpose epilogue with fused bias+residual.
// ---------------------------------------------------------------------------
#define PJ_BHI    10240    // byte offset within a stage
#define PJ_STAGEB 18944
#define PJ_SMEM   75776    // 4 stages; transpose needs 67584 <= this

__global__ __launch_bounds__(256) void k_proj(const float* __restrict__ bo,
                                              const float* __restrict__ x,
                                              float* __restrict__ out)
{
    extern __shared__ __align__(16) uint16_t smp[];
    const int tid  = threadIdx.x;
    const int lane = tid & 31;
    const int wid  = tid >> 5;
    const int bx   = blockIdx.x;    // bn tile 0..63
    const int by   = blockIdx.y;    // c tile 0..3
    const int b    = bx >> 3;
    const int c0   = by * 128;
    const int bn0  = bx * 128;
    const uint32_t sb = (uint32_t)__cvta_generic_to_shared(smp);

    // loader mapping
    const int am = tid >> 1;
    const int ak = (tid & 1) * 16;            // u16
    const size_t aG = (size_t)(bn0 + am) * CC + ak;
    const int bk = tid >> 3;
    const int bn = (tid & 7) * 16;            // u16
    const size_t bG = (size_t)bk * CC + c0 + bn;
    const uint32_t dAp = (uint32_t)(am * 40 + ak) * 2;
    const uint32_t dBp = PJ_BHI + (uint32_t)(bk * 136 + bn) * 2;

#define PJ_ISSUE(s) do {                                                      \
        uint32_t st = sb + ((s) & 3) * PJ_STAGEB;                             \
        const uint16_t* ah = &g_ah[aG + (s) * 32];                            \
        const uint16_t* bh = &g_woh[bG + (size_t)(s) * 32 * CC];              \
        cpa16(st + dAp, ah);             cpa16(st + dAp + 16, ah + 8);        \
        cpa16(st + dBp, bh);             cpa16(st + dBp + 16, bh + 8);        \
    } while (0)

    const int wm = wid >> 2;
    const int wn = wid & 3;
    const uint32_t aOff = (wm * 64 + (lane & 15)) * 80 + (lane >> 4) * 16;
    const uint32_t bOff = PJ_BHI + ((lane & 7) + (((lane >> 3) & 1) << 3)) * 272
                        + (uint32_t)(wn * 64) + (lane >> 4) * 16;

    float acc[4][4][4];
#pragma unroll
    for (int i = 0; i < 4; i++)
#pragma unroll
        for (int j = 0; j < 4; j++)
#pragma unroll
            for (int e = 0; e < 4; e++) acc[i][j][e] = 0.f;

    PJ_ISSUE(0); CP_COMMIT();
    PJ_ISSUE(1); CP_COMMIT();
    PJ_ISSUE(2); CP_COMMIT();

    for (int s = 0; s < 16; s++) {
        CP_WAIT_TAIL(s, 15);
        __syncthreads();
        if (s + 3 < 16) { PJ_ISSUE(s + 3); CP_COMMIT(); }

        const uint32_t base = sb + (uint32_t)(s & 3) * PJ_STAGEB;
#pragma unroll
        for (int ks = 0; ks < 2; ks++) {
            uint32_t ahi[4][4], bhi[4][2];
#pragma unroll
            for (int i = 0; i < 4; i++) {
                uint32_t a = base + aOff + i * (16 * 80) + ks * 32;
                ldmx4(a, ahi[i]);
            }
#pragma unroll
            for (int j2 = 0; j2 < 2; j2++) {
                uint32_t a = base + bOff + ks * 4352 + j2 * 32;
                ldmx4t(a, bhi[2 * j2][0], bhi[2 * j2][1], bhi[2 * j2 + 1][0], bhi[2 * j2 + 1][1]);
            }
#pragma unroll
            for (int i = 0; i < 4; i++)
#pragma unroll
                for (int jn = 0; jn < 4; jn++)
                    mma16816(acc[i][jn], ahi[i], bhi[jn]);
        }
    }

    // ---- epilogue: transpose via smem, fused bias + residual ----
    __syncthreads();
    float* S = (float*)smp;   // [128 c][stride 132] of m
    const int g   = lane >> 2;
    const int tig = lane & 3;
#pragma unroll
    for (int i = 0; i < 4; i++) {
        int m_l = wm * 64 + i * 16 + g;
#pragma unroll
        for (int jn = 0; jn < 4; jn++) {
            int c_l = wn * 32 + jn * 8 + tig * 2;
            S[c_l * 132 + m_l]           = acc[i][jn][0];
            S[(c_l + 1) * 132 + m_l]     = acc[i][jn][1];
            S[c_l * 132 + m_l + 8]       = acc[i][jn][2];
            S[(c_l + 1) * 132 + m_l + 8] = acc[i][jn][3];
        }
    }
    __syncthreads();
    {
        const int c_l  = tid >> 1;
        const int mseg = (tid & 1) * 64;
        const int c    = c0 + c_l;
        const float bias = bo[c];
        const int n0 = (bx & 7) * 128;
        const size_t basep = (size_t)b * CC * NN + (size_t)c * NN + n0 + mseg;
#pragma unroll
        for (int i = 0; i < 16; i++) {
            float4 v  = *(float4*)&S[c_l * 132 + mseg + 4 * i];
            float4 xr = *(const float4*)&x[basep + 4 * i];
            v.x += bias + xr.x; v.y += bias + xr.y;
            v.z += bias + xr.z; v.w += bias + xr.w;
            *(float4*)&out[basep + 4 * i] = v;
        }
    }
}

// ---------------------------------------------------------------------------
extern "C" void kernel_launch(void* const* d_in, const int* in_sizes, int n_in,
                              void* d_out, int out_size)
{
    const float* x  = (const float*)d_in[0];
    const float* Wq = (const float*)d_in[1];
    const float* bq = (const float*)d_in[2];
    const float* Wo = (const float*)d_in[3];
    const float* bo = (const float*)d_in[4];
    float* out = (float*)d_out;

    k_cvt<<<(NX4 + NWQ4 + NWO4 + 255) / 256, 256>>>(x, Wq, Wo);

    cudaFuncSetAttribute(k_qkv, cudaFuncAttributeMaxDynamicSharedMemorySize, QK_SMEM);
    k_qkv<<<dim3(12, 64), 256, QK_SMEM>>>(bq);

    cudaFuncSetAttribute(k_attn, cudaFuncAttributeMaxDynamicSharedMemorySize, A_SMEM_BYTES);
    k_attn<<<dim3(8, HEADS, BB), 256, A_SMEM_BYTES>>>();

    cudaFuncSetAttribute(k_proj, cudaFuncAttributeMaxDynamicSharedMemorySize, PJ_SMEM);
    k_proj<<<dim3(64, 4), 256, PJ_SMEM>>>(bo, x, out);
}